// round 17
// baseline (speedup 1.0000x reference)
#include <cuda_runtime.h>
#include <cuda_fp16.h>
#include <cstdint>

// ---------------- problem constants ----------------
#define BATCH   4
#define CIN     128
#define COUT    128
#define HDIM    128
#define WDIM    128
#define HW      (HDIM * WDIM)      // 16384
#define NGROUP  4
#define CG      32
#define KTAPS   9
#define RTOT    (CIN * KTAPS)      // 1152 = 72 * 16
#define NSTEP   72                 // k16 steps
#define HSTEP   36                 // steps per k-half
#define TPX     32                 // pixels (N) per block
#define NTHREADS 256
#define NQUADS  (BATCH * (CIN / 4))            // 128 channel quads
#define XR_U128 ((size_t)NQUADS * HW)          // 2,097,152 u128 entries

// ---------------- smem layout (bytes) ----------------
// S (samples, f16 single plane): [1152 k][64 B swizzled row] = 73728
// sacc (partial fp32 accs) aliases S after GEMM: 128 x 33 floats
// misc @ 73728: ss0(128), ss1(128), swo(576)
#define SMEM_S_OFF   0
#define SMEM_MISC    73728
#define OFF_SS0      (SMEM_MISC + 0)
#define OFF_SS1      (SMEM_MISC + 128)
#define OFF_SWO      (SMEM_MISC + 256)
#define SMEM_BYTES   (SMEM_MISC + 832)   // 74560  (x3 CTAs = 223,680)
#define SACC_STRIDE  33

// Weights pre-packed in m16n8k16 A-fragment order, single f16 plane:
// uint4 idx = (step*8 + otile)*32 + lane
__device__ __align__(16) uint32_t g_wAf32[NSTEP * 8 * 32 * 4];   // 294912 B

// Channel-quad + x-pair packed f16 x:
// u128 entry [chquad][i] = { h2(c0: x[i],x[i+1]), h2(c1: ...), h2(c2: ...), h2(c3: ...) }
// c0..c3 = 4*chquad .. +3 (global channels). One LDG.128 = 4 channels x 2 x-corners.
__device__ __align__(16) uint4 g_xr[XR_U128];                    // 33.5 MB

__device__ __forceinline__ uint32_t smem_to_u32(const void* p) {
    uint32_t a;
    asm("{ .reg .u64 t; cvta.to.shared.u64 t, %1; cvt.u32.u64 %0, t; }" : "=r"(a) : "l"(p));
    return a;
}

// S swizzle: row k is 64B (32 px f16), 4 x 16B chunks; chunk ^= (k>>1)&3 so
// ldmatrix's 8-row phases hit disjoint 16B groups.
__device__ __forceinline__ int s_off(int k, int px) {
    return (k << 6) + ((px & 7) << 1) + ((((px >> 3) ^ ((k >> 1) & 3))) << 4);
}

__device__ __forceinline__ void ldsm_x4_trans(uint32_t* r, uint32_t addr) {
    asm volatile("ldmatrix.sync.aligned.m8n8.x4.trans.shared.b16 {%0,%1,%2,%3}, [%4];"
                 : "=r"(r[0]), "=r"(r[1]), "=r"(r[2]), "=r"(r[3]) : "r"(addr));
}
__device__ __forceinline__ void mma_f16(float* c, const uint32_t* a, uint32_t b0, uint32_t b1) {
    asm volatile(
        "mma.sync.aligned.m16n8k16.row.col.f32.f16.f16.f32 "
        "{%0,%1,%2,%3}, {%4,%5,%6,%7}, {%8,%9}, {%0,%1,%2,%3};"
        : "+f"(c[0]), "+f"(c[1]), "+f"(c[2]), "+f"(c[3])
        : "r"(a[0]), "r"(a[1]), "r"(a[2]), "r"(a[3]), "r"(b0), "r"(b1));
}

__device__ __forceinline__ uint32_t pack_h2(float a, float b) {
    __half2 h = __floats2half2_rn(a, b);
    return *reinterpret_cast<uint32_t*>(&h);
}
__device__ __forceinline__ float2 h2f(uint32_t u) {
    return __half22float2(*reinterpret_cast<__half2*>(&u));
}

// ---------------- prep 0: x -> channel-quad/x-pair u128 array ----------------
// thread t covers 4 consecutive i of one channel quad (outputs 4 u128 = 64 B)
__global__ void prep_xr_kernel(const float* __restrict__ x) {
    size_t t  = (size_t)blockIdx.x * 256 + threadIdx.x;   // 524,288 threads
    size_t e0 = t * 4;                  // first u128 index
    size_t i  = e0 & (HW - 1);          // i within channel
    size_t cq = e0 >> 14;               // channel quad (global)
    const float* p = x + (cq * 4) * (size_t)HW + i;
    float a[4][5];
    #pragma unroll
    for (int c = 0; c < 4; c++) {
        float4 v = *reinterpret_cast<const float4*>(p + (size_t)c * HW);
        a[c][0] = v.x; a[c][1] = v.y; a[c][2] = v.z; a[c][3] = v.w;
        a[c][4] = (i + 4 < HW) ? p[(size_t)c * HW + 4] : 0.0f;
    }
    uint4* outp = reinterpret_cast<uint4*>(g_xr) + t * 4;
    #pragma unroll
    for (int j = 0; j < 4; j++) {       // i offset
        uint4 o;
        o.x = pack_h2(a[0][j], a[0][j + 1]);
        o.y = pack_h2(a[1][j], a[1][j + 1]);
        o.z = pack_h2(a[2][j], a[2][j + 1]);
        o.w = pack_h2(a[3][j], a[3][j + 1]);
        outp[j] = o;
    }
}

// ---------------- prep: weights -> A-fragment layout, f16 ----------------
__global__ void prep_wAf_kernel(const float* __restrict__ wd) {
    int idx = blockIdx.x * 256 + threadIdx.x;       // b32 index
    if (idx >= NSTEP * 8 * 32 * 4) return;
    int q     = idx & 3;
    int lane  = (idx >> 2) & 31;
    int ot    = (idx >> 7) & 7;
    int step  = idx >> 10;
    int g = lane >> 2, t = lane & 3;
    int row = ot * 16 + g + ((q & 1) << 3);
    int col = step * 16 + t * 2 + ((q >> 1) << 3);
    __half h0 = __float2half_rn(wd[row * RTOT + col]);
    __half h1 = __float2half_rn(wd[row * RTOT + col + 1]);
    g_wAf32[idx] = ((uint32_t)reinterpret_cast<unsigned short&>(h1) << 16)
                 |  (uint32_t)reinterpret_cast<unsigned short&>(h0);
}

// ---------------- main kernel ----------------
__global__ void __launch_bounds__(NTHREADS, 3)
deform_kernel(const float* __restrict__ x,        // unused (g_xr)
              const float* __restrict__ shape,    // [B,2,H,W]
              const float* __restrict__ w_offset, // [72][2]
              float* __restrict__ out)            // [B,COUT,H,W]
{
    extern __shared__ char smem[];
    const uint32_t smem_u32 = smem_to_u32(smem);
    float* ss0  = (float*)(smem + OFF_SS0);
    float* ss1  = (float*)(smem + OFF_SS1);
    float* swo  = (float*)(smem + OFF_SWO);
    float* sacc = (float*)(smem + SMEM_S_OFF);   // alias of S, used after GEMM

    const int tid = threadIdx.x;
    const int wid = tid >> 5;
    const int lid = tid & 31;

    const int b   = blockIdx.x >> 9;
    const int rem = blockIdx.x & 511;
    const int h   = rem >> 2;
    const int w0  = (rem & 3) << 5;

    // ---- stage small tables ----
    if (tid < 32)                     ss0[tid]     = shape[(size_t)(b*2+0)*HW + h*WDIM + w0 + tid];
    else if (tid < 64)                ss1[tid-32]  = shape[(size_t)(b*2+1)*HW + h*WDIM + w0 + (tid-32)];
    else if (tid >= 64 && tid < 208)  swo[tid-64]  = w_offset[tid-64];
    __syncthreads();

    // ---- phase A: sample via u128 quad loads -> f16 swizzled S [1152][32] ----
    for (int i = tid; i < 36 * TPX; i += NTHREADS) {
        int gk = i >> 5, px = i & 31;
        int g  = gk / 9, k = gk - g * 9;
        int ky = k / 3,  kx = k - ky * 3;
        float s0 = ss0[px], s1 = ss1[px];
        float offy = swo[gk*4 + 0] * s0 + swo[gk*4 + 1] * s1;
        float offx = swo[gk*4 + 2] * s0 + swo[gk*4 + 3] * s1;
        float py  = offy + (float)(ky - 1 + h);
        float pxf = offx + (float)(kx - 1 + w0 + px);
        float y0f = floorf(py), x0f = floorf(pxf);
        float fy = py - y0f, fx = pxf - x0f;
        int y0 = (int)y0f, x0 = (int)x0f;

        // per-row y weights (zeroed when row out of bounds)
        float wy0 = (y0     >= 0 && y0     <= 127) ? (1.0f - fy) : 0.0f;
        float wy1 = (y0 + 1 >= 0 && y0 + 1 <= 127) ? fy          : 0.0f;
        int yc0 = min(max(y0,     0), 127);
        int yc1 = min(max(y0 + 1, 0), 127);

        // x-pair weights: one packed pair at xb covers both x-corners
        int xb = min(max(x0, 0), 126);
        float wl, wr;
        if (x0 >= 0 && x0 <= 126)      { wl = 1.0f - fx; wr = fx;          }
        else if (x0 == -1)             { wl = fx;        wr = 0.0f;        }
        else if (x0 == 127)            { wl = 0.0f;      wr = 1.0f - fx;   }
        else                           { wl = 0.0f;      wr = 0.0f;        }

        float w00 = wy0 * wl, w01 = wy0 * wr;
        float w10 = wy1 * wl, w11 = wy1 * wr;
        int i0 = yc0 * WDIM + xb;
        int i1 = yc1 * WDIM + xb;

        // channel-quad base for this (b, g): quad = b*32 + g*8
        const uint4* xq = g_xr + ((size_t)(b * 32 + g * 8)) * HW;
        const int r0 = (g * CG) * KTAPS + k;     // r for cg=0; stride 9 per cg
        #pragma unroll 2
        for (int cgq = 0; cgq < 8; cgq++) {
            const uint4* xc = xq + (size_t)cgq * HW;
            uint4 q0 = xc[i0];      // 4 channels, row y0
            uint4 q1 = xc[i1];      // 4 channels, row y1
            const uint32_t* u0 = (const uint32_t*)&q0;
            const uint32_t* u1 = (const uint32_t*)&q1;
            #pragma unroll
            for (int j = 0; j < 4; j++) {
                float2 f0 = h2f(u0[j]);
                float2 f1 = h2f(u1[j]);
                float v = w00 * f0.x + w01 * f0.y + w10 * f1.x + w11 * f1.y;
                int r  = r0 + (4 * cgq + j) * KTAPS;
                *(__half*)(smem + SMEM_S_OFF + s_off(r, px)) = __float2half_rn(v);
            }
        }
    }
    __syncthreads();

    // ---- phase B: 8 warps = 2 k-halves x 4 o-quarters, tile o32 x n32 ----
    const int kw    = wid >> 2;          // k-half
    const int ow    = wid & 3;           // o-quarter (o = ow*32 .. +31)
    const int bkrow = lid & 15;
    const int bsel  = lid >> 4;

    const uint4* gA = reinterpret_cast<const uint4*>(g_wAf32);

    float acc[2][4][4];
    #pragma unroll
    for (int a1 = 0; a1 < 2; a1++)
        #pragma unroll
        for (int a2 = 0; a2 < 4; a2++)
            #pragma unroll
            for (int a3 = 0; a3 < 4; a3++) acc[a1][a2][a3] = 0.0f;

    const int step0 = kw * HSTEP;
    for (int s = 0; s < HSTEP; s++) {
        const int step = step0 + s;

        uint4 A0 = gA[((step * 8 + (ow << 1) + 0) << 5) + lid];
        uint4 A1 = gA[((step * 8 + (ow << 1) + 1) << 5) + lid];

        const int k = (step << 4) + bkrow;
        uint32_t bf[2][4];
        #pragma unroll
        for (int half = 0; half < 2; half++) {
            int bnchk = (half << 1) + bsel;
            int boff  = (k << 6) + (((bnchk ^ ((k >> 1) & 3))) << 4);
            ldsm_x4_trans(bf[half], smem_u32 + SMEM_S_OFF + (uint32_t)boff);
        }

        const uint32_t* a0 = (const uint32_t*)&A0;
        const uint32_t* a1 = (const uint32_t*)&A1;
        mma_f16(acc[0][0], a0, bf[0][0], bf[0][1]);
        mma_f16(acc[0][1], a0, bf[0][2], bf[0][3]);
        mma_f16(acc[0][2], a0, bf[1][0], bf[1][1]);
        mma_f16(acc[0][3], a0, bf[1][2], bf[1][3]);
        mma_f16(acc[1][0], a1, bf[0][0], bf[0][1]);
        mma_f16(acc[1][1], a1, bf[0][2], bf[0][3]);
        mma_f16(acc[1][2], a1, bf[1][0], bf[1][1]);
        mma_f16(acc[1][3], a1, bf[1][2], bf[1][3]);
    }
    __syncthreads();    // all LDSM from S done; S now reusable as sacc

    // ---- reduction: kw==1 dumps partials; kw==0 adds + ReLU + stores ----
    // acc[ot][j] covers n8 tile j at px = j*8
    const int g = lid >> 2, t = lid & 3;
    if (kw == 1) {
        #pragma unroll
        for (int ot = 0; ot < 2; ot++) {
            #pragma unroll
            for (int j = 0; j < 4; j++) {
                int o  = (ow << 5) + (ot << 4) + g;
                int px = (j << 3) + (t << 1);
                sacc[ o      * SACC_STRIDE + px    ] = acc[ot][j][0];
                sacc[ o      * SACC_STRIDE + px + 1] = acc[ot][j][1];
                sacc[(o + 8) * SACC_STRIDE + px    ] = acc[ot][j][2];
                sacc[(o + 8) * SACC_STRIDE + px + 1] = acc[ot][j][3];
            }
        }
    }
    __syncthreads();
    if (kw == 0) {
        #pragma unroll
        for (int ot = 0; ot < 2; ot++) {
            #pragma unroll
            for (int j = 0; j < 4; j++) {
                int o  = (ow << 5) + (ot << 4) + g;
                int px = (j << 3) + (t << 1);
                float* op0 = out + (((size_t)b * COUT + o) << 14) + (h << 7) + w0 + px;
                float* op1 = op0 + ((size_t)8 << 14);   // row o+8
                float2 v0, v1;
                v0.x = fmaxf(acc[ot][j][0] + sacc[ o      * SACC_STRIDE + px    ], 0.0f);
                v0.y = fmaxf(acc[ot][j][1] + sacc[ o      * SACC_STRIDE + px + 1], 0.0f);
                v1.x = fmaxf(acc[ot][j][2] + sacc[(o + 8) * SACC_STRIDE + px    ], 0.0f);
                v1.y = fmaxf(acc[ot][j][3] + sacc[(o + 8) * SACC_STRIDE + px + 1], 0.0f);
                *reinterpret_cast<float2*>(op0) = v0;
                *reinterpret_cast<float2*>(op1) = v1;
            }
        }
    }
}

extern "C" void kernel_launch(void* const* d_in, const int* in_sizes, int n_in,
                              void* d_out, int out_size) {
    const float* x        = (const float*)d_in[0];
    const float* shape    = (const float*)d_in[1];
    const float* w_offset = (const float*)d_in[2];
    const float* w_deform = (const float*)d_in[3];
    float* out = (float*)d_out;

    cudaFuncSetAttribute(deform_kernel,
                         cudaFuncAttributeMaxDynamicSharedMemorySize, SMEM_BYTES);

    prep_xr_kernel<<<(int)((XR_U128 / 4) / 256), 256>>>(x);
    prep_wAf_kernel<<<(NSTEP * 8 * 32 * 4 + 255) / 256, 256>>>(w_deform);

    const int nblocks = BATCH * HDIM * (WDIM / TPX);   // 2048
    deform_kernel<<<nblocks, NTHREADS, SMEM_BYTES>>>(x, shape, w_offset, out);
}